// round 1
// baseline (speedup 1.0000x reference)
#include <cuda_runtime.h>

#define BATCH 512
#define INF   512
#define OUTF  100
#define KD    5
#define OKC   500           // OUTF * KD
#define LOG2E 1.4426950408889634f

// Scratch: M in [o][b][k] layout, pre-scaled by log2(e).
__device__ float g_M[OUTF * BATCH * KD];

__device__ __forceinline__ float ex2_approx(float x) {
    float y;
    asm("ex2.approx.ftz.f32 %0, %1;" : "=f"(y) : "f"(x));
    return y;
}

// ---------------------------------------------------------------------------
// Kernel 1: M[o][b][k] = LOG2E * sum_i x[b][i] * T[i][o*KD+k]
// Tile: 32 (m) x 64 (n), BK=16, 256 threads, thread tile 2x4.
// grid = (ceil(500/64)=8, 512/32=16) = 128 blocks.
// ---------------------------------------------------------------------------
__global__ void __launch_bounds__(256)
gemm_kernel(const float* __restrict__ x, const float* __restrict__ W) {
    __shared__ float As[16][32];   // x^T tile: As[kk][m]
    __shared__ float Bs[16][64];   // W tile:   Bs[kk][n]

    const int m0 = blockIdx.y * 32;
    const int n0 = blockIdx.x * 64;
    const int tid = threadIdx.x;
    const int tx = tid & 15;       // n direction (4 cols each)
    const int ty = tid >> 4;       // m direction (2 rows each)

    float acc[2][4] = {};

    for (int kt = 0; kt < INF; kt += 16) {
        // Load A tile: 32x16 = 512 elems, 2 per thread.
        #pragma unroll
        for (int idx = tid; idx < 32 * 16; idx += 256) {
            int m  = idx >> 4;
            int kk = idx & 15;
            As[kk][m] = x[(m0 + m) * INF + kt + kk];
        }
        // Load B tile: 16x64 = 1024 elems, 4 per thread (bounds: 500 cols).
        #pragma unroll
        for (int idx = tid; idx < 16 * 64; idx += 256) {
            int kk = idx >> 6;
            int n  = idx & 63;
            int c  = n0 + n;
            Bs[kk][n] = (c < OKC) ? W[(kt + kk) * OKC + c] : 0.0f;
        }
        __syncthreads();

        #pragma unroll
        for (int kk = 0; kk < 16; kk++) {
            float a0 = As[kk][ty * 2 + 0];
            float a1 = As[kk][ty * 2 + 1];
            float4 bv = reinterpret_cast<const float4*>(&Bs[kk][0])[tx];
            acc[0][0] += a0 * bv.x;
            acc[0][1] += a0 * bv.y;
            acc[0][2] += a0 * bv.z;
            acc[0][3] += a0 * bv.w;
            acc[1][0] += a1 * bv.x;
            acc[1][1] += a1 * bv.y;
            acc[1][2] += a1 * bv.z;
            acc[1][3] += a1 * bv.w;
        }
        __syncthreads();
    }

    // Store, rearranging column c = o*5+k into [o][b][k] layout, scaled by log2e.
    #pragma unroll
    for (int ii = 0; ii < 2; ii++) {
        int m = m0 + ty * 2 + ii;
        #pragma unroll
        for (int jj = 0; jj < 4; jj++) {
            int c = n0 + tx * 4 + jj;
            if (c < OKC) {
                int o = c / KD;
                int k = c - o * KD;
                g_M[o * (BATCH * KD) + m * KD + k] = acc[ii][jj] * LOG2E;
            }
        }
    }
}

// ---------------------------------------------------------------------------
// Kernel 2: out[j][o] = sum_i exp2(-sum_k |M[i,o,k]-M[j,o,k]|) - 1
// One block handles one o and a slice of 128 j's. grid = (100, 4), 128 thr.
// M rows staged in smem with stride 8 (pads zeroed) -> aligned LDS.128.
// ---------------------------------------------------------------------------
__global__ void __launch_bounds__(128)
pairwise_kernel(float* __restrict__ out) {
    const int o = blockIdx.x;
    const int j = blockIdx.y * 128 + threadIdx.x;

    __shared__ float sM[BATCH * 8];   // 16 KB, rows padded 5 -> 8

    const float* base = g_M + o * (BATCH * KD);

    // Zero the pad lanes.
    for (int b = threadIdx.x; b < BATCH; b += 128) {
        sM[b * 8 + 5] = 0.0f;
        sM[b * 8 + 6] = 0.0f;
        sM[b * 8 + 7] = 0.0f;
    }
    // Stage the 512x5 tile (coalesced gmem reads).
    for (int idx = threadIdx.x; idx < BATCH * KD; idx += 128) {
        int b = idx / KD;
        int k = idx - b * KD;
        sM[b * 8 + k] = base[idx];
    }
    __syncthreads();

    const float m0 = sM[j * 8 + 0];
    const float m1 = sM[j * 8 + 1];
    const float m2 = sM[j * 8 + 2];
    const float m3 = sM[j * 8 + 3];
    const float m4 = sM[j * 8 + 4];

    const float4* s4 = reinterpret_cast<const float4*>(sM);

    float acc = 0.0f;
    #pragma unroll 8
    for (int i = 0; i < BATCH; i++) {
        float4 a  = s4[i * 2];          // k = 0..3 (broadcast across warp)
        float  a4 = sM[i * 8 + 4];      // k = 4
        float norm = fabsf(a.x - m0)
                   + fabsf(a.y - m1)
                   + fabsf(a.z - m2)
                   + fabsf(a.w - m3)
                   + fabsf(a4  - m4);
        acc += ex2_approx(-norm);       // M pre-scaled by log2e
    }

    // Self term is exactly exp2(0) = 1.
    out[j * OUTF + o] = acc - 1.0f;
}

// ---------------------------------------------------------------------------
extern "C" void kernel_launch(void* const* d_in, const int* in_sizes, int n_in,
                              void* d_out, int out_size) {
    const float* x = (const float*)d_in[0];   // [512, 512]
    const float* T = (const float*)d_in[1];   // [512, 100, 5] == [512, 500]
    float* out = (float*)d_out;               // [512, 100]

    dim3 ggrid((OKC + 63) / 64, BATCH / 32);  // (8, 16) = 128 blocks
    gemm_kernel<<<ggrid, 256>>>(x, T);

    dim3 pgrid(OUTF, BATCH / 128);            // (100, 4) = 400 blocks
    pairwise_kernel<<<pgrid, 128>>>(out);
}

// round 2
// speedup vs baseline: 1.2567x; 1.2567x over previous
#include <cuda_runtime.h>

#define BATCH 512
#define INF   512
#define OUTF  100
#define KD    5
#define OKC   500           // OUTF * KD
#define LOG2E 1.4426950408889634f

// Split-K partial GEMM results, [plane][o][b][k], pre-scaled by log2(e).
__device__ float g_Mp[2][OUTF * BATCH * KD];

__device__ __forceinline__ float ex2_approx(float x) {
    float y;
    asm("ex2.approx.ftz.f32 %0, %1;" : "=f"(y) : "f"(x));
    return y;
}

// ---------------------------------------------------------------------------
// Kernel 1: split-K GEMM.
// g_Mp[kz][o][b][k] = LOG2E * sum_{i in K-half kz} x[b][i] * T[i][o*KD+k]
// Tile: 32 (m) x 64 (n), BK=16, 256 threads, thread tile 2x4.
// grid = (8, 16, 2) = 256 blocks.
// ---------------------------------------------------------------------------
__global__ void __launch_bounds__(256)
gemm_kernel(const float* __restrict__ x, const float* __restrict__ W) {
    __shared__ float As[16][32];   // x^T tile: As[kk][m]
    __shared__ float Bs[16][64];   // W tile:   Bs[kk][n]

    const int m0 = blockIdx.y * 32;
    const int n0 = blockIdx.x * 64;
    const int k0 = blockIdx.z * 256;       // K-half
    const int tid = threadIdx.x;
    const int tx = tid & 15;               // n direction (4 cols each)
    const int ty = tid >> 4;               // m direction (2 rows each)

    float acc[2][4] = {};

    for (int kt = 0; kt < 256; kt += 16) {
        // A tile: 32x16 = 512 elems, 2 per thread (coalesced along k).
        #pragma unroll
        for (int idx = tid; idx < 32 * 16; idx += 256) {
            int m  = idx >> 4;
            int kk = idx & 15;
            As[kk][m] = x[(m0 + m) * INF + k0 + kt + kk];
        }
        // B tile: 16x64 = 1024 elems, 4 per thread (bounds: 500 cols).
        #pragma unroll
        for (int idx = tid; idx < 16 * 64; idx += 256) {
            int kk = idx >> 6;
            int n  = idx & 63;
            int c  = n0 + n;
            Bs[kk][n] = (c < OKC) ? W[(k0 + kt + kk) * OKC + c] : 0.0f;
        }
        __syncthreads();

        #pragma unroll
        for (int kk = 0; kk < 16; kk++) {
            float2 av = *reinterpret_cast<const float2*>(&As[kk][ty * 2]);
            float4 bv = reinterpret_cast<const float4*>(&Bs[kk][0])[tx];
            acc[0][0] += av.x * bv.x;
            acc[0][1] += av.x * bv.y;
            acc[0][2] += av.x * bv.z;
            acc[0][3] += av.x * bv.w;
            acc[1][0] += av.y * bv.x;
            acc[1][1] += av.y * bv.y;
            acc[1][2] += av.y * bv.z;
            acc[1][3] += av.y * bv.w;
        }
        __syncthreads();
    }

    // Store, rearranging column c = o*5+k into [o][b][k] layout, scaled by log2e.
    float* plane = g_Mp[blockIdx.z];
    #pragma unroll
    for (int ii = 0; ii < 2; ii++) {
        int m = m0 + ty * 2 + ii;
        #pragma unroll
        for (int jj = 0; jj < 4; jj++) {
            int c = n0 + tx * 4 + jj;
            if (c < OKC) {
                int o = c / KD;
                int k = c - o * KD;
                plane[o * (BATCH * KD) + m * KD + k] = acc[ii][jj] * LOG2E;
            }
        }
    }
}

// ---------------------------------------------------------------------------
// Kernel 2: out[j][o] += sum_{i in i-slice} exp2(-sum_k |M[i,o,k]-M[j,o,k]|)
// grid = (100 o, 2 j-slices of 256, 4 i-slices of 128), 256 threads.
// The i-slice (128 rows x 5, padded to stride 8) is staged in 4KB smem.
// Partials accumulated into out via atomicAdd; out pre-zeroed by memset.
// Self term exp2(0)=1 removed by acc=-1 init in the slice containing i=j.
// ---------------------------------------------------------------------------
__global__ void __launch_bounds__(256)
pairwise_kernel(float* __restrict__ out) {
    const int o  = blockIdx.x;
    const int j  = blockIdx.y * 256 + threadIdx.x;
    const int i0 = blockIdx.z * 128;

    __shared__ float sM[128 * 8];   // 4 KB, rows padded 5 -> 8 (pads never read)

    const float* base0 = g_Mp[0] + o * (BATCH * KD);
    const float* base1 = g_Mp[1] + o * (BATCH * KD);

    // Stage the i-slice (128 rows), summing the two split-K planes.
    #pragma unroll
    for (int idx = threadIdx.x; idx < 128 * KD; idx += 256) {
        int b = idx / KD;
        int k = idx - b * KD;
        int g = (i0 + b) * KD + k;
        sM[b * 8 + k] = base0[g] + base1[g];
    }
    __syncthreads();

    // This thread's own row, straight from gmem.
    const float m0 = base0[j * KD + 0] + base1[j * KD + 0];
    const float m1 = base0[j * KD + 1] + base1[j * KD + 1];
    const float m2 = base0[j * KD + 2] + base1[j * KD + 2];
    const float m3 = base0[j * KD + 3] + base1[j * KD + 3];
    const float m4 = base0[j * KD + 4] + base1[j * KD + 4];

    const float4* s4 = reinterpret_cast<const float4*>(sM);

    // Self term (i == j) lands in the i-slice blockIdx.z == j/128: exp2(0)=1.
    float acc = ((j >> 7) == blockIdx.z) ? -1.0f : 0.0f;

    #pragma unroll 8
    for (int i = 0; i < 128; i++) {
        float4 a  = s4[i * 2];          // k = 0..3 (warp-uniform broadcast)
        float  a4 = sM[i * 8 + 4];      // k = 4
        float norm = fabsf(a.x - m0)
                   + fabsf(a.y - m1)
                   + fabsf(a.z - m2)
                   + fabsf(a.w - m3)
                   + fabsf(a4  - m4);
        acc += ex2_approx(-norm);       // M pre-scaled by log2e
    }

    atomicAdd(&out[j * OUTF + o], acc);
}

// ---------------------------------------------------------------------------
extern "C" void kernel_launch(void* const* d_in, const int* in_sizes, int n_in,
                              void* d_out, int out_size) {
    const float* x = (const float*)d_in[0];   // [512, 512]
    const float* T = (const float*)d_in[1];   // [512, 100, 5] == [512, 500]
    float* out = (float*)d_out;               // [512, 100]

    cudaMemsetAsync(out, 0, BATCH * OUTF * sizeof(float));

    dim3 ggrid((OKC + 63) / 64, BATCH / 32, 2);   // 256 blocks
    gemm_kernel<<<ggrid, 256>>>(x, T);

    dim3 pgrid(OUTF, BATCH / 256, 4);             // 800 blocks
    pairwise_kernel<<<pgrid, 256>>>(out);
}

// round 3
// speedup vs baseline: 1.4937x; 1.1886x over previous
#include <cuda_runtime.h>

#define BATCH 512
#define INF   512
#define OUTF  100
#define KD    5
#define OKC   500            // OUTF * KD
#define PLANE (OKC * BATCH)  // 256000
#define NZ    4              // split-K factor
#define LOG2E 1.4426950408889634f

typedef unsigned long long u64;

// Split-K partial GEMM results, [z][c][b] with c = o*KD + k, pre-scaled by log2e.
__device__ float g_Mp[NZ][PLANE];

// ---- packed f32x2 helpers (FFMA2/FADD2 on sm_103a) ----
__device__ __forceinline__ u64 f2add(u64 a, u64 b) {
    u64 r; asm("add.rn.f32x2 %0,%1,%2;" : "=l"(r) : "l"(a), "l"(b)); return r;
}
__device__ __forceinline__ u64 f2fma(u64 a, u64 b, u64 c) {
    u64 r; asm("fma.rn.f32x2 %0,%1,%2,%3;" : "=l"(r) : "l"(a), "l"(b), "l"(c)); return r;
}
__device__ __forceinline__ u64 pk(float lo, float hi) {
    u64 r; asm("mov.b64 %0,{%1,%2};" : "=l"(r) : "f"(lo), "f"(hi)); return r;
}
__device__ __forceinline__ void upk(u64 a, float& lo, float& hi) {
    asm("mov.b64 {%0,%1},%2;" : "=f"(lo), "=f"(hi) : "l"(a));
}
__device__ __forceinline__ float ex2_approx(float x) {
    float y; asm("ex2.approx.ftz.f32 %0, %1;" : "=f"(y) : "f"(x)); return y;
}
#define NEGABS_MASK 0x8000000080000000ULL   // OR -> -(|x|) on both halves

// ---------------------------------------------------------------------------
// Kernel 1: split-K GEMM with packed FFMA2.
// g_Mp[z][c][b] = LOG2E * sum_{k in K-slice z} X[b][k] * W[k][c]
// Block tile 64(m) x 64(n), BK=16, K-slice = 128, 256 threads, 4x4/thread.
// A duplicated in smem as (a,a) pairs; acc packed along n. Double-buffered.
// grid = (8, 8, 4) = 256 blocks.
// ---------------------------------------------------------------------------
__global__ void __launch_bounds__(256)
gemm_kernel(const float* __restrict__ X, const float* __restrict__ W) {
    __shared__ float Asd[2][16][128];  // [buf][kk][2m] duplicated A (8 KB x2)
    __shared__ float Bs [2][16][64];   // [buf][kk][n]               (4 KB x2)

    const int tid = threadIdx.x;
    const int tx  = tid & 15;          // n quad
    const int ty  = tid >> 4;          // m quad
    const int m0  = blockIdx.y * 64;
    const int n0  = blockIdx.x * 64;
    const int k0  = blockIdx.z * 128;

    // load assignments
    const int am = tid >> 2;           // A: row m (0..63)
    const int ak = (tid & 3) * 4;      // A: k quad within BK
    const int bk = tid >> 4;           // B: kk row (0..15)
    const int bc = n0 + (tid & 15) * 4;// B: global col quad
    const bool bok = bc < OKC;

    const float* xp = X + (m0 + am) * INF + k0 + ak;
    const float* wp = W + (k0 + bk) * OKC + bc;

    // prologue: tile 0 -> buf 0
    float4 av = *(const float4*)xp;
    float4 bv = bok ? *(const float4*)wp : make_float4(0.f, 0.f, 0.f, 0.f);
    {
        *(float2*)&Asd[0][ak + 0][2 * am] = make_float2(av.x, av.x);
        *(float2*)&Asd[0][ak + 1][2 * am] = make_float2(av.y, av.y);
        *(float2*)&Asd[0][ak + 2][2 * am] = make_float2(av.z, av.z);
        *(float2*)&Asd[0][ak + 3][2 * am] = make_float2(av.w, av.w);
        *(float4*)&Bs[0][bk][tid & 15 ? (tid & 15) * 4 : 0] = bv;  // (tx*4)
    }
    __syncthreads();

    u64 acc[4][2];
    #pragma unroll
    for (int i = 0; i < 4; i++) { acc[i][0] = 0ULL; acc[i][1] = 0ULL; }

    for (int kt = 0; kt < 8; kt++) {
        const int cur = kt & 1;
        if (kt < 7) {
            av = *(const float4*)(xp + (kt + 1) * 16);
            bv = bok ? *(const float4*)(wp + (kt + 1) * 16 * OKC)
                     : make_float4(0.f, 0.f, 0.f, 0.f);
        }
        #pragma unroll
        for (int kk = 0; kk < 16; kk++) {
            float4 a01 = *(const float4*)&Asd[cur][kk][ty * 8];
            float4 a23 = *(const float4*)&Asd[cur][kk][ty * 8 + 4];
            float4 b   = *(const float4*)&Bs[cur][kk][tx * 4];
            u64 b0 = pk(b.x, b.y);
            u64 b1 = pk(b.z, b.w);
            u64 a0 = pk(a01.x, a01.y);
            u64 a1 = pk(a01.z, a01.w);
            u64 a2 = pk(a23.x, a23.y);
            u64 a3 = pk(a23.z, a23.w);
            acc[0][0] = f2fma(a0, b0, acc[0][0]);
            acc[0][1] = f2fma(a0, b1, acc[0][1]);
            acc[1][0] = f2fma(a1, b0, acc[1][0]);
            acc[1][1] = f2fma(a1, b1, acc[1][1]);
            acc[2][0] = f2fma(a2, b0, acc[2][0]);
            acc[2][1] = f2fma(a2, b1, acc[2][1]);
            acc[3][0] = f2fma(a3, b0, acc[3][0]);
            acc[3][1] = f2fma(a3, b1, acc[3][1]);
        }
        if (kt < 7) {
            const int nxt = cur ^ 1;
            *(float2*)&Asd[nxt][ak + 0][2 * am] = make_float2(av.x, av.x);
            *(float2*)&Asd[nxt][ak + 1][2 * am] = make_float2(av.y, av.y);
            *(float2*)&Asd[nxt][ak + 2][2 * am] = make_float2(av.z, av.z);
            *(float2*)&Asd[nxt][ak + 3][2 * am] = make_float2(av.w, av.w);
            *(float4*)&Bs[nxt][bk][(tid & 15) * 4] = bv;
            __syncthreads();
        }
    }

    // epilogue: unpack and store column-major [c][b], scaled by log2e.
    float r[4][4];  // r[mi][j] = C[m0+ty*4+mi][n0+tx*4+j]
    #pragma unroll
    for (int mi = 0; mi < 4; mi++) {
        upk(acc[mi][0], r[mi][0], r[mi][1]);
        upk(acc[mi][1], r[mi][2], r[mi][3]);
    }
    float* plane = g_Mp[blockIdx.z];
    #pragma unroll
    for (int j = 0; j < 4; j++) {
        int c = n0 + tx * 4 + j;
        if (c < OKC) {
            float4 o = make_float4(r[0][j] * LOG2E, r[1][j] * LOG2E,
                                   r[2][j] * LOG2E, r[3][j] * LOG2E);
            *(float4*)&plane[c * BATCH + m0 + ty * 4] = o;
        }
    }
}

// ---------------------------------------------------------------------------
// Kernel 2: out[j][o] += sum_{i in slice} exp2(-sum_k |M[i,o,k]-M[j,o,k]|)
// Packed f32x2: 2 pairs per lane-op; abs as 64-bit sign-OR on alu pipe.
// grid = (100 o, 2 j-slices of 256, 4 i-slices of 128), 256 threads.
// ---------------------------------------------------------------------------
__global__ void __launch_bounds__(256)
pairwise_kernel(float* __restrict__ out) {
    const int o  = blockIdx.x;
    const int j  = blockIdx.y * 256 + threadIdx.x;
    const int i0 = blockIdx.z * 128;

    __shared__ float sA[KD][128];   // SoA: 2.5 KB

    const float* base = g_Mp[0] + o * KD * BATCH;

    // stage i-slice, summing the 4 split-K planes (coalesced).
    #pragma unroll
    for (int idx = threadIdx.x; idx < KD * 128; idx += 256) {
        int k = idx >> 7, b = idx & 127;
        int g = k * BATCH + i0 + b;
        sA[k][b] = base[g] + base[PLANE + g] + base[2 * PLANE + g] + base[3 * PLANE + g];
    }

    // own row, duplicated & negated into packed regs.
    u64 nm[KD];
    #pragma unroll
    for (int k = 0; k < KD; k++) {
        int g = k * BATCH + j;
        float m = base[g] + base[PLANE + g] + base[2 * PLANE + g] + base[3 * PLANE + g];
        nm[k] = pk(-m, -m);
    }
    __syncthreads();

    u64 accv = 0ULL;
    #pragma unroll 4
    for (int i = 0; i < 128; i += 4) {
        float4 q0 = *(const float4*)&sA[0][i];
        float4 q1 = *(const float4*)&sA[1][i];
        float4 q2 = *(const float4*)&sA[2][i];
        float4 q3 = *(const float4*)&sA[3][i];
        float4 q4 = *(const float4*)&sA[4][i];
        #pragma unroll
        for (int h = 0; h < 2; h++) {
            u64 p0 = h ? pk(q0.z, q0.w) : pk(q0.x, q0.y);
            u64 p1 = h ? pk(q1.z, q1.w) : pk(q1.x, q1.y);
            u64 p2 = h ? pk(q2.z, q2.w) : pk(q2.x, q2.y);
            u64 p3 = h ? pk(q3.z, q3.w) : pk(q3.x, q3.y);
            u64 p4 = h ? pk(q4.z, q4.w) : pk(q4.x, q4.y);
            u64 n0v = f2add(p0, nm[0]) | NEGABS_MASK;   // -(|d|) both halves
            u64 n1v = f2add(p1, nm[1]) | NEGABS_MASK;
            u64 n2v = f2add(p2, nm[2]) | NEGABS_MASK;
            u64 n3v = f2add(p3, nm[3]) | NEGABS_MASK;
            u64 n4v = f2add(p4, nm[4]) | NEGABS_MASK;
            u64 s = f2add(f2add(n0v, n1v), f2add(n2v, n3v));
            s = f2add(s, n4v);                          // = (-norm0, -norm1)
            float s0, s1; upk(s, s0, s1);
            accv = f2add(accv, pk(ex2_approx(s0), ex2_approx(s1)));
        }
    }

    float alo, ahi; upk(accv, alo, ahi);
    float r = alo + ahi;
    if ((j >> 7) == (int)blockIdx.z) r -= 1.0f;   // remove self term exp2(-0)=1
    atomicAdd(&out[j * OUTF + o], r);
}

// ---------------------------------------------------------------------------
extern "C" void kernel_launch(void* const* d_in, const int* in_sizes, int n_in,
                              void* d_out, int out_size) {
    const float* x = (const float*)d_in[0];   // [512, 512]
    const float* T = (const float*)d_in[1];   // [512, 100, 5] == [512, 500]
    float* out = (float*)d_out;               // [512, 100]

    cudaMemsetAsync(out, 0, BATCH * OUTF * sizeof(float));

    dim3 ggrid(8, 8, NZ);                     // 256 blocks
    gemm_kernel<<<ggrid, 256>>>(x, T);

    dim3 pgrid(OUTF, BATCH / 256, 4);         // 800 blocks
    pairwise_kernel<<<pgrid, 256>>>(out);
}